// round 11
// baseline (speedup 1.0000x reference)
#include <cuda_runtime.h>
#include <math.h>

// ---------------------------------------------------------------------------
// SCRFD post-processing, fully fused into ONE persistent kernel:
//   decode+hist -> bucket scan -> bucket fill -> exact rank+scatter ->
//   edges + unmasked output -> (block0) NMS + masked fixup + state reset
//
// Grid barriers: software (monotonic counters). 132 blocks <= 148 SMs, one
// 512-thread block per SM => co-residency guaranteed, no deadlock. Counters
// are reset by block 0 at the very end; at the final barrier non-zero blocks
// only ARRIVE and exit (never spin), so the reset cannot race a spinner.
//
// Output layout (float32, 134400 elems):
//   [0:33600) boxes[8400,4] | [33600:42000) scores | [42000:126000) kps[8400,10]
//   | [126000:134400) keep
// ---------------------------------------------------------------------------

#define NTOT   8400
#define NBLK   132
#define NTHR   512
#define NBUCK  4096          // bucket = f32 bits >> 18 (all keys positive)
#define BSHIFT 18
#define SCORE_T 0.5f
#define NMS_T   0.4f
#define EDGE_CAP (1 << 22)
#define ESMEM   8192         // edges cached in smem when ne <= this

typedef unsigned long long u64;
typedef unsigned int u32;
typedef unsigned char uc;

__device__ float4 g_box[NTOT];         // decoded boxes (orig order)
__device__ float  g_kps[NTOT * 10];    // decoded keypoints (orig order)
__device__ u32    g_key32[NTOT];       // sigmoid f32 bits (positive)
__device__ u32    g_hist[NBUCK];       // zeroed at end of prev run / static init
__device__ u32    g_hcnt[NBUCK];       // bucket fill cursors (zeroed likewise)
__device__ u32    g_bbase[NBUCK];      // descending-order exclusive bases
__device__ u64    g_bitem[NTOT];       // (key<<14)|(8399-n) per bucket
__device__ float  g_skey[NTOT];        // sorted scores
__device__ int    g_sidx[NTOT];        // sorted -> orig index
__device__ float4 g_sbox[NTOT];        // sorted boxes
__device__ float  g_area[NTOT];        // sorted areas
__device__ int    g_nedges;            // zeroed at end of prev run
__device__ u32    g_edges[EDGE_CAP];   // (i<<16)|j, j<i, IoU>NMS_T, i valid
__device__ u32    g_ctr[8];            // barrier counters (zeroed at end)

// Software grid barrier: all blocks arrive then spin until count==NBLK.
__device__ __forceinline__ void gsync(int id)
{
    __syncthreads();
    if (threadIdx.x == 0) {
        __threadfence();                       // release prior writes
        atomicAdd(&g_ctr[id], 1u);
        while (*(volatile u32*)&g_ctr[id] < NBLK) __nanosleep(32);
    }
    __syncthreads();
    __threadfence();                           // acquire side
}

__global__ __launch_bounds__(NTHR, 1)
void fused_kernel(const float* __restrict__ s0, const float* __restrict__ b0, const float* __restrict__ k0,
                  const float* __restrict__ s1, const float* __restrict__ b1, const float* __restrict__ k1,
                  const float* __restrict__ s2, const float* __restrict__ b2, const float* __restrict__ k2,
                  float* __restrict__ out)
{
    extern __shared__ char smem[];
    const int tid = threadIdx.x;
    const int gid = blockIdx.x * NTHR + tid;

    // ---------------- Phase A: decode + histogram -------------------------
    // (g_hist / g_hcnt / g_nedges / g_ctr are zero: static init on first run,
    //  reset by block 0 at the end of every run.)
    if (gid < NTOT) {
        int n = gid;
        const float *sp, *bp, *kp;
        int local, fw;
        float st;
        if (n < 6400)      { sp = s0; bp = b0; kp = k0; local = n;        fw = 80; st = 8.0f;  }
        else if (n < 8000) { sp = s1; bp = b1; kp = k1; local = n - 6400; fw = 40; st = 16.0f; }
        else               { sp = s2; bp = b2; kp = k2; local = n - 8000; fw = 20; st = 32.0f; }

        float px = (float)(local % fw) * st;     // exact (int * pow2)
        float py = (float)(local / fw) * st;

        // sigmoid in double: correctly-rounded-to-f32 -> monotone ordering
        // (ordering verified vs JAX in R7-R9, rel_err 4.3e-8).
        float s = (float)(1.0 / (1.0 + exp(-(double)sp[local])));

        float4 d = ((const float4*)bp)[local];   // strides pow2 -> bit-exact
        float4 bb;
        bb.x = px - d.x * st;
        bb.y = py - d.y * st;
        bb.z = px + d.z * st;
        bb.w = py + d.w * st;
        g_box[n] = bb;

#pragma unroll
        for (int q = 0; q < 10; q++) {
            float base = (q & 1) ? py : px;
            g_kps[n * 10 + q] = base + kp[local * 10 + q] * st;
        }

        u32 key = __float_as_uint(s);            // positive -> int order = float order
        g_key32[n] = key;
        atomicAdd(&g_hist[key >> BSHIFT], 1u);
    }
    gsync(0);

    // ---------------- Phase B: descending exclusive scan (block 0) --------
    if (blockIdx.x == 0) {
        u32* sc = (u32*)smem;                    // 512 u32
        u32 loc[8];
        u32 s = 0;
#pragma unroll
        for (int q = 0; q < 8; q++) {            // descending bucket order
            int b = NBUCK - 1 - (tid * 8 + q);
            loc[q] = g_hist[b];
            s += loc[q];
        }
        sc[tid] = s;
        __syncthreads();
        for (int off = 1; off < NTHR; off <<= 1) {
            u32 v = sc[tid];
            u32 add = (tid >= off) ? sc[tid - off] : 0u;
            __syncthreads();
            sc[tid] = v + add;
            __syncthreads();
        }
        u32 run = sc[tid] - s;                   // exclusive
#pragma unroll
        for (int q = 0; q < 8; q++) {
            int b = NBUCK - 1 - (tid * 8 + q);
            g_bbase[b] = run;
            run += loc[q];
        }
    }
    gsync(1);

    // ---------------- Phase C: fill bucket lists --------------------------
    if (gid < NTOT) {
        u32 key = g_key32[gid];
        u32 b = key >> BSHIFT;
        u32 slot = atomicAdd(&g_hcnt[b], 1u);    // slot order irrelevant
        g_bitem[g_bbase[b] + slot] = ((u64)key << 14) | (u32)(NTOT - 1 - gid);
    }
    gsync(2);

    // ---------------- Phase D: exact rank within bucket + scatter ---------
    // rank(n) = bbase[b] + #{ items in bucket : pack > mine }
    // pack order: key desc, then idx asc (via NTOT-1-n). Exact permutation.
    if (gid < NTOT) {
        u32 key = g_key32[gid];
        u32 b = key >> BSHIFT;
        u32 base = g_bbase[b];
        u32 L = g_hist[b];
        u64 me = ((u64)key << 14) | (u32)(NTOT - 1 - gid);
        u32 c = 0;
        for (u32 l = 0; l < L; l++)
            c += (g_bitem[base + l] > me) ? 1u : 0u;
        u32 r = base + c;
        g_skey[r] = __uint_as_float(key);
        g_sidx[r] = gid;
        float4 bx = g_box[gid];
        g_sbox[r] = bx;
        g_area[r] = __fmul_rn(__fsub_rn(bx.z, bx.x), __fsub_rn(bx.w, bx.y));
    }
    gsync(3);

    // ---------------- Phase E: suppression edges + unmasked output --------
    // Edges (i,j): j<i, IoU>NMS_T, i valid (validity is a prefix of the
    // descending sort -> break at first invalid i in this block's stripe).
    // IoU replicates JAX bit-for-bit (rn intrinsics block FMA contraction).
    for (int i = blockIdx.x; i < NTOT; i += NBLK) {
        if (g_skey[i] <= SCORE_T) break;
        if (i == 0) continue;
        float4 bi = g_sbox[i];
        float  ai = g_area[i];
        for (int j = tid; j < i; j += NTHR) {
            float4 bj = g_sbox[j];
            float ltx = fmaxf(bi.x, bj.x);
            float lty = fmaxf(bi.y, bj.y);
            float rbx = fminf(bi.z, bj.z);
            float rby = fminf(bi.w, bj.w);
            float w = fmaxf(__fsub_rn(rbx, ltx), 0.0f);
            float h = fmaxf(__fsub_rn(rby, lty), 0.0f);
            float inter = __fmul_rn(w, h);
            if (inter > 0.0f) {
                float denom = __fadd_rn(__fsub_rn(__fadd_rn(ai, g_area[j]), inter), 1e-9f);
                float iou = __fdiv_rn(inter, denom);
                if (iou > NMS_T) {
                    int pos = atomicAdd(&g_nedges, 1);
                    if (pos < EDGE_CAP) g_edges[pos] = ((u32)i << 16) | (u32)j;
                }
            }
        }
    }
    // Unmasked outputs in parallel (block 0 fixes suppressed rows later).
    for (int p = gid; p < NTOT; p += NBLK * NTHR) {
        float4 b = g_sbox[p];
        out[p * 4 + 0] = b.x;
        out[p * 4 + 1] = b.y;
        out[p * 4 + 2] = b.z;
        out[p * 4 + 3] = b.w;
        out[33600 + p] = g_skey[p];
        int j = g_sidx[p];
#pragma unroll
        for (int q = 0; q < 10; q++)
            out[42000 + p * 10 + q] = g_kps[j * 10 + q];
    }

    // ---------------- Final barrier: arrive-only, non-zero blocks exit ----
    __syncthreads();
    __threadfence();
    if (tid == 0) atomicAdd(&g_ctr[4], 1u);
    if (blockIdx.x != 0) return;

    if (tid == 0)
        while (*(volatile u32*)&g_ctr[4] < NBLK) __nanosleep(32);
    __syncthreads();
    __threadfence();

    // ---------------- Phase F (block 0): NMS fixpoint in smem -------------
    // keep[i] = valid[i] && !any((i,j) edge: keep[j]) — unique fixpoint on
    // the j<i DAG; Jacobi iterate, "no change" = exact; NTOT+1 cap = hard.
    {
        u32* es   = (u32*)smem;                  // [ESMEM]
        uc* valid = (uc*)(es + ESMEM);           // [NTOT]
        uc* keep  = valid + NTOT;                // [NTOT]
        uc* sup   = keep + NTOT;                 // [NTOT]
        __shared__ int changed;

        int ne = g_nedges;
        if (ne > EDGE_CAP) ne = EDGE_CAP;
        bool use_s = (ne <= ESMEM);
        if (use_s)
            for (int e = tid; e < ne; e += NTHR) es[e] = g_edges[e];
        for (int p = tid; p < NTOT; p += NTHR) {
            uc v = (g_skey[p] > SCORE_T) ? 1 : 0;
            valid[p] = v;
            keep[p] = v;
        }
        __syncthreads();
        const u32* E = use_s ? es : g_edges;

        for (int it = 0; it < NTOT + 1; it++) {
            if (tid == 0) changed = 0;
            for (int e = tid; e < ne; e += NTHR) sup[E[e] >> 16] = 0;
            __syncthreads();
            for (int e = tid; e < ne; e += NTHR) {
                u32 x = E[e];
                if (keep[x & 0xffffu]) sup[x >> 16] = 1;
            }
            __syncthreads();
            for (int e = tid; e < ne; e += NTHR) {
                int i = (int)(E[e] >> 16);
                uc nv = (valid[i] && !sup[i]) ? 1 : 0;
                if (keep[i] != nv) { keep[i] = nv; changed = 1; }
            }
            __syncthreads();
            int ch = changed;
            __syncthreads();
            if (!ch) break;
        }

        // ------------- Phase G: masked fixup + keep column ----------------
        for (int p = tid; p < NTOT; p += NTHR) {
            uc m = keep[p];
            out[126000 + p] = m ? 1.0f : 0.0f;
            if (!m) {
                out[p * 4 + 0] = 0.0f;
                out[p * 4 + 1] = 0.0f;
                out[p * 4 + 2] = 0.0f;
                out[p * 4 + 3] = 0.0f;
                out[33600 + p] = 0.0f;
#pragma unroll
                for (int q = 0; q < 10; q++)
                    out[42000 + p * 10 + q] = 0.0f;
            }
        }
        __syncthreads();

        // ------------- Reset device state for the next graph replay -------
        // All other blocks have exited (they arrived at ctr[4] and returned,
        // and had passed every earlier spin), so no one can observe these.
        for (int q = tid; q < NBUCK; q += NTHR) { g_hist[q] = 0; g_hcnt[q] = 0; }
        if (tid < 8) g_ctr[tid] = 0;
        if (tid == 0) g_nedges = 0;
    }
}

// ---------------------------------------------------------------------------
extern "C" void kernel_launch(void* const* d_in, const int* in_sizes, int n_in,
                              void* d_out, int out_size)
{
    const float *s0, *b0, *k0, *s1, *b1, *k1, *s2, *b2, *k2;
    // dict-insertion order (score0,bbox0,kps0,...) vs signature order
    if (n_in >= 9 && in_sizes[1] == 25600) {
        s0 = (const float*)d_in[0]; b0 = (const float*)d_in[1]; k0 = (const float*)d_in[2];
        s1 = (const float*)d_in[3]; b1 = (const float*)d_in[4]; k1 = (const float*)d_in[5];
        s2 = (const float*)d_in[6]; b2 = (const float*)d_in[7]; k2 = (const float*)d_in[8];
    } else {
        s0 = (const float*)d_in[0]; s1 = (const float*)d_in[1]; s2 = (const float*)d_in[2];
        b0 = (const float*)d_in[3]; b1 = (const float*)d_in[4]; b2 = (const float*)d_in[5];
        k0 = (const float*)d_in[6]; k1 = (const float*)d_in[7]; k2 = (const float*)d_in[8];
    }

    const int smem = ESMEM * 4 + 3 * NTOT + 256;     // NMS arrays (max phase), ~58KB
    cudaFuncSetAttribute(fused_kernel, cudaFuncAttributeMaxDynamicSharedMemorySize,
                         smem);                      // immediate host API, idempotent

    fused_kernel<<<NBLK, NTHR, smem>>>(s0, b0, k0, s1, b1, k1, s2, b2, k2, (float*)d_out);
}